// round 11
// baseline (speedup 1.0000x reference)
#include <cuda_runtime.h>
#include <cuda_fp16.h>
#include <cstdint>

// Soft decision tree forward via mma.sync fp16 (family-common sm_103;
// tcgen05 unavailable in this toolchain path).
// Chain nodes (2^k)-1, k=0..5 -> N = 6*64 = 384.
// GEMM H = X[65536 x 128] @ W1cat[128 x 384], fp16 -> fp32 accumulate.
// Fused epilogue: relu -> dot W2 -> sigmoid -> 6-level leaf fold.
// R11: R9 structure (persistent 128 CTAs x 4 M=128 tiles, W staged once,
// raw-X prefetch) but 512 threads / 16 warps (96 accs/thread, 128-reg cap)
// -> 4 warps/SMSP. Warp tile = 64 rows x 48 cols; epilogue merges per-node
// partials via shared atomicAdd.

#define THREADS 512
#define M_CTA   128
#define KDIM    128
#define NTOT    384
#define NCTAS   128
#define TILES   4
#define XPITCH  288      // bytes/row (72 words): conflict-free lds64
#define WPITCH  288

// W1 (live nodes) fp16, [n=384][k=128], k permuted within 16-blocks so that
// pairs (2t4,2t4+1) and (2t4+8,2t4+9) are adjacent -> frags = one LDS.64.
__device__ __align__(16) __half g_Wh[NTOT * KDIM];

// ---- smem layout (bytes) ----
#define OFF_B1    0
#define OFF_W2    1536
#define OFF_B2    3072
#define OFF_LEAF  3104
#define OFF_RS    3360                 // rowsum 6*132*4 = 3168 -> 6528
#define OFF_XC    6656                 // converted X: 128 * 288 = 36864
#define OFF_W     43520                // W: 384 * 288 = 110592
#define OFF_XR    154112               // raw X: 128 rows * 512B = 65536
#define SMEM_BYTES 219648              // ~214.5 KB, 1 CTA/SM

// ---------------- helpers ----------------
__device__ __forceinline__ uint32_t smem_u32_of(const void* p) {
    uint32_t a;
    asm("{ .reg .u64 t; cvta.to.shared.u64 t, %1; cvt.u32.u64 %0, t; }"
        : "=r"(a) : "l"(p));
    return a;
}
__device__ __forceinline__ void cp_async16(uint32_t dst, const void* src) {
    asm volatile("cp.async.cg.shared.global [%0], [%1], 16;" :: "r"(dst), "l"(src));
}
__device__ __forceinline__ void lds64(uint32_t& a, uint32_t& b, uint32_t addr) {
    asm volatile("ld.shared.v2.u32 {%0,%1}, [%2];" : "=r"(a), "=r"(b) : "r"(addr));
}
__device__ __forceinline__ void sts32(uint32_t addr, uint32_t v) {
    asm volatile("st.shared.u32 [%0], %1;" :: "r"(addr), "r"(v));
}
__device__ __forceinline__ void mma_fp16(float* c, const uint32_t* a,
                                         uint32_t b0, uint32_t b1) {
    asm volatile(
        "mma.sync.aligned.m16n8k16.row.col.f32.f16.f16.f32 "
        "{%0,%1,%2,%3}, {%4,%5,%6,%7}, {%8,%9}, {%0,%1,%2,%3};"
        : "+f"(c[0]), "+f"(c[1]), "+f"(c[2]), "+f"(c[3])
        : "r"(a[0]), "r"(a[1]), "r"(a[2]), "r"(a[3]), "r"(b0), "r"(b1));
}

// ---------------- pre-kernel: W1 -> fp16, permuted k ----------------
__global__ void convert_w1_kernel(const float* __restrict__ W1) {
    int idx = blockIdx.x * blockDim.x + threadIdx.x;
    if (idx >= NTOT * KDIM) return;
    int k = idx & 127;
    int n = idx >> 7;
    int node = n >> 6, h = n & 63;
    int gnode = (1 << node) - 1;            // 0,1,3,7,15,31
    float v = W1[(size_t)gnode * (KDIM * 64) + (size_t)k * 64 + h];
    int blk = k >> 4, kk = k & 15, q = kk >> 1;
    int pos = (q & 3) * 2 + (q >> 2);
    g_Wh[n * KDIM + blk * 16 + pos * 2 + (kk & 1)] = __float2half_rn(v);
}

// ---------------- main kernel ----------------
__global__ __launch_bounds__(THREADS, 1)
void sdt_fp16_kernel(const float* __restrict__ x,
                     const float* __restrict__ b1,
                     const float* __restrict__ W2,
                     const float* __restrict__ b2,
                     const float* __restrict__ leaf,
                     float* __restrict__ out)
{
    extern __shared__ char smem[];
    const uint32_t sbase = smem_u32_of(smem);
    float* b1sh   = (float*)(smem + OFF_B1);
    float* W2s    = (float*)(smem + OFF_W2);
    float* b2s    = (float*)(smem + OFF_B2);
    float* leafs  = (float*)(smem + OFF_LEAF);
    float* rowsum = (float*)(smem + OFF_RS);

    const int tid  = threadIdx.x;
    const int lane = tid & 31;
    const int wid  = tid >> 5;
    const int wm   = wid & 1;               // M half (64 rows)
    const int ws   = wid >> 1;              // N strip (48 cols), 0..7
    const int g    = lane >> 2;
    const int t4   = lane & 3;
    const int bx   = blockIdx.x;

    // ---- prologue: stage W (once) + raw X tile 0 via cp.async ----
    #pragma unroll
    for (int it = 0; it < 12; it++) {
        int idx = tid + it * THREADS;       // 0..6143
        int row = idx >> 4, v = idx & 15;
        cp_async16(sbase + OFF_W + row * WPITCH + v * 16,
                   g_Wh + row * KDIM + v * 8);
    }
    {
        const float* xt = x + (size_t)bx * TILES * M_CTA * KDIM;
        #pragma unroll
        for (int it = 0; it < 8; it++) {
            int idx = tid + it * THREADS;   // 0..4095
            int row = idx >> 5, v = idx & 31;
            cp_async16(sbase + OFF_XR + row * 512 + v * 16,
                       xt + row * KDIM + v * 4);
        }
    }
    asm volatile("cp.async.commit_group;" ::: "memory");

    // small tensors for the 6 live nodes
    for (int i = tid; i < NTOT; i += THREADS) {
        int node = i >> 6, h = i & 63;
        int gl = ((1 << node) - 1) * 64 + h;
        b1sh[i] = b1[gl];
        W2s[i]  = W2[gl];
    }
    if (tid < 6)  b2s[tid]   = b2[(1 << tid) - 1];
    if (tid < 64) leafs[tid] = leaf[tid];

    asm volatile("cp.async.wait_group 0;" ::: "memory");
    __syncthreads();

    const uint32_t xb = sbase + OFF_XC + (uint32_t)((wm * 64 + g) * XPITCH + t4 * 8);
    const uint32_t wb = sbase + OFF_W  + (uint32_t)((ws * 48 + g) * WPITCH + t4 * 8);
    const int c0    = ws * 48;              // strip base column
    const int nodeA = c0 >> 6;
    const int two   = (((c0 + 40) >> 6) != nodeA);

    for (int ti = 0; ti < TILES; ti++) {
        const int rowbase = (bx * TILES + ti) * M_CTA;

        // ---- convert raw X -> fp16 interleaved Xcvt; zero rowsum ----
        #pragma unroll
        for (int it = 0; it < 8; it++) {
            int idx = tid + it * THREADS;   // 0..4095
            int row = idx >> 5, c4 = idx & 31;
            float4 v = *(const float4*)(smem + OFF_XR + row * 512 + c4 * 16);
            __half2 h01 = __floats2half2_rn(v.x, v.y);
            __half2 h23 = __floats2half2_rn(v.z, v.w);
            int blk = c4 >> 2, m = c4 & 3;
            int pos_a = (m & 1) * 4 + (m >> 1);
            uint32_t a = sbase + OFF_XC + row * XPITCH + blk * 32 + pos_a * 4;
            sts32(a,     *(uint32_t*)&h01);
            sts32(a + 8, *(uint32_t*)&h23);
        }
        for (int i = tid; i < 6 * 132; i += THREADS) rowsum[i] = 0.0f;
        __syncthreads();

        // ---- prefetch raw X for next tile (overlaps MMA below) ----
        if (ti + 1 < TILES) {
            const float* xt = x + (size_t)(bx * TILES + ti + 1) * M_CTA * KDIM;
            #pragma unroll
            for (int it = 0; it < 8; it++) {
                int idx = tid + it * THREADS;
                int row = idx >> 5, v = idx & 31;
                cp_async16(sbase + OFF_XR + row * 512 + v * 16,
                           xt + row * KDIM + v * 4);
            }
            asm volatile("cp.async.commit_group;" ::: "memory");
        }

        // ---- MMA: 8 k-steps over full k=128; warp tile 64 x 48 ----
        float acc[4][6][4];
        #pragma unroll
        for (int mt = 0; mt < 4; mt++)
            #pragma unroll
            for (int nt = 0; nt < 6; nt++)
                #pragma unroll
                for (int j = 0; j < 4; j++) acc[mt][nt][j] = 0.0f;

        #pragma unroll
        for (int ks = 0; ks < 8; ks++) {
            const uint32_t ko = (uint32_t)(ks * 32);
            uint32_t A[4][4];
            #pragma unroll
            for (int mt = 0; mt < 4; mt++) {
                lds64(A[mt][0], A[mt][2], xb + (uint32_t)(mt * 16 * XPITCH) + ko);
                lds64(A[mt][1], A[mt][3], xb + (uint32_t)(mt * 16 * XPITCH) + 8 * XPITCH + ko);
            }
            #pragma unroll
            for (int nt = 0; nt < 6; nt++) {
                uint32_t b0, b1v_;
                lds64(b0, b1v_, wb + (uint32_t)(nt * 8 * WPITCH) + ko);
                #pragma unroll
                for (int mt = 0; mt < 4; mt++)
                    mma_fp16(acc[mt][nt], A[mt], b0, b1v_);
            }
        }

        // ---- epilogue: per-node partial dots, merge via shared atomics ----
        {
            float sA[4][2], sB[4][2];
            #pragma unroll
            for (int mt = 0; mt < 4; mt++) {
                sA[mt][0] = sA[mt][1] = 0.0f;
                sB[mt][0] = sB[mt][1] = 0.0f;
            }
            #pragma unroll
            for (int nt = 0; nt < 6; nt++) {
                int colb = c0 + nt * 8;
                int col  = colb + t4 * 2;
                float ba  = b1sh[col], bb = b1sh[col + 1];
                float w2a = W2s[col],  w2b = W2s[col + 1];
                bool isA  = ((colb >> 6) == nodeA);
                #pragma unroll
                for (int mt = 0; mt < 4; mt++) {
                    float v0 = fmaf(fmaxf(acc[mt][nt][0] + ba, 0.0f), w2a,
                                    fmaxf(acc[mt][nt][1] + bb, 0.0f) * w2b);
                    float v1 = fmaf(fmaxf(acc[mt][nt][2] + ba, 0.0f), w2a,
                                    fmaxf(acc[mt][nt][3] + bb, 0.0f) * w2b);
                    if (isA) { sA[mt][0] += v0; sA[mt][1] += v1; }
                    else     { sB[mt][0] += v0; sB[mt][1] += v1; }
                }
            }
            #pragma unroll
            for (int mt = 0; mt < 4; mt++) {
                #pragma unroll
                for (int h = 0; h < 2; h++) {
                    float a = sA[mt][h], b = sB[mt][h];
                    a += __shfl_xor_sync(0xffffffffu, a, 1);
                    a += __shfl_xor_sync(0xffffffffu, a, 2);
                    b += __shfl_xor_sync(0xffffffffu, b, 1);
                    b += __shfl_xor_sync(0xffffffffu, b, 2);
                    if (t4 == 0) {
                        int r = wm * 64 + mt * 16 + g + h * 8;
                        atomicAdd(&rowsum[nodeA * 132 + r], a);
                        if (two) atomicAdd(&rowsum[(nodeA + 1) * 132 + r], b);
                    }
                }
            }
        }
        __syncthreads();

        if (tid < M_CTA) {
            float p[6];
            #pragma unroll
            for (int k = 0; k < 6; k++) {
                float z = rowsum[k * 132 + tid] + b2s[k];
                p[k] = 1.0f / (1.0f + __expf(-z));
            }
            float v[32];
            #pragma unroll
            for (int m = 0; m < 32; m++)
                v[m] = fmaf(p[0], leafs[2 * m + 1], (1.0f - p[0]) * leafs[2 * m]);
            #pragma unroll
            for (int k = 1; k < 6; k++) {
                int len = 32 >> k;
                #pragma unroll
                for (int m = 0; m < 32; m++)
                    if (m < len)
                        v[m] = fmaf(p[k], v[2 * m + 1], (1.0f - p[k]) * v[2 * m]);
            }
            out[rowbase + tid] = v[0];
        }

        if (ti + 1 < TILES)
            asm volatile("cp.async.wait_group 0;" ::: "memory");
        __syncthreads();
    }
}

// ---------------- launch ----------------
extern "C" void kernel_launch(void* const* d_in, const int* in_sizes, int n_in,
                              void* d_out, int out_size)
{
    const float* x    = (const float*)d_in[0];
    const float* W1   = (const float*)d_in[1];
    const float* b1   = (const float*)d_in[2];
    const float* W2   = (const float*)d_in[3];
    const float* b2   = (const float*)d_in[4];
    const float* leaf = (const float*)d_in[5];
    float* out = (float*)d_out;

    cudaFuncSetAttribute(sdt_fp16_kernel, cudaFuncAttributeMaxDynamicSharedMemorySize, SMEM_BYTES);

    convert_w1_kernel<<<(NTOT * KDIM + 255) / 256, 256>>>(W1);
    sdt_fp16_kernel<<<NCTAS, THREADS, SMEM_BYTES>>>(x, b1, W2, b2, leaf, out);
}

// round 12
// speedup vs baseline: 1.6388x; 1.6388x over previous
#include <cuda_runtime.h>
#include <cuda_fp16.h>
#include <cstdint>

// Soft decision tree forward via mma.sync fp16 (family-common sm_103;
// tcgen05 unavailable in this toolchain path).
// Chain nodes (2^k)-1, k=0..5 -> N = 6*64 = 384.
// GEMM H = X[65536 x 128] @ W1cat[128 x 384], fp16 -> fp32 accumulate.
// Fused epilogue: relu -> dot W2 -> sigmoid -> 6-level leaf fold.
// R12: R9 persistent structure (128 CTAs x 4 M=128 tiles, W once, X prefetch)
// + N-split accumulators (64 regs, two passes/tile) -> freed RF spent on
// double-buffered fragment pipelining + hoisted linear addressing.

#define THREADS 384      // 12 warps: wm = wid&1 (M half), wn = wid>>1 (node)
#define M_CTA   128
#define KDIM    128
#define NTOT    384
#define NCTAS   128
#define TILES   4
#define XPITCH  288      // bytes/row (72 words): conflict-free lds64
#define WPITCH  288

// W1 (live nodes) fp16, [n=384][k=128], k permuted within 16-blocks so that
// pairs (2t4,2t4+1) and (2t4+8,2t4+9) are adjacent -> frags = one LDS.64.
__device__ __align__(16) __half g_Wh[NTOT * KDIM];

// ---- smem layout (bytes) ----
#define OFF_B1    0
#define OFF_W2    1536
#define OFF_B2    3072
#define OFF_LEAF  3104
#define OFF_RS    3360                 // rowsum 6*132*4 = 3168 -> 6528
#define OFF_XC    6656                 // converted X: 128 * 288 = 36864
#define OFF_W     43520                // W: 384 * 288 = 110592
#define OFF_XR    154112               // raw X: 128 rows * 512B = 65536
#define SMEM_BYTES 219648              // ~214.5 KB, 1 CTA/SM

// ---------------- helpers ----------------
__device__ __forceinline__ uint32_t smem_u32_of(const void* p) {
    uint32_t a;
    asm("{ .reg .u64 t; cvta.to.shared.u64 t, %1; cvt.u32.u64 %0, t; }"
        : "=r"(a) : "l"(p));
    return a;
}
__device__ __forceinline__ void cp_async16(uint32_t dst, const void* src) {
    asm volatile("cp.async.cg.shared.global [%0], [%1], 16;" :: "r"(dst), "l"(src));
}
__device__ __forceinline__ void lds64(uint32_t& a, uint32_t& b, uint32_t addr) {
    asm volatile("ld.shared.v2.u32 {%0,%1}, [%2];" : "=r"(a), "=r"(b) : "r"(addr));
}
__device__ __forceinline__ void lds128f(float4& v, uint32_t addr) {
    asm volatile("ld.shared.v4.f32 {%0,%1,%2,%3}, [%4];"
                 : "=f"(v.x), "=f"(v.y), "=f"(v.z), "=f"(v.w) : "r"(addr));
}
__device__ __forceinline__ void sts32(uint32_t addr, uint32_t v) {
    asm volatile("st.shared.u32 [%0], %1;" :: "r"(addr), "r"(v));
}
__device__ __forceinline__ void mma_fp16(float* c, const uint32_t* a,
                                         uint32_t b0, uint32_t b1) {
    asm volatile(
        "mma.sync.aligned.m16n8k16.row.col.f32.f16.f16.f32 "
        "{%0,%1,%2,%3}, {%4,%5,%6,%7}, {%8,%9}, {%0,%1,%2,%3};"
        : "+f"(c[0]), "+f"(c[1]), "+f"(c[2]), "+f"(c[3])
        : "r"(a[0]), "r"(a[1]), "r"(a[2]), "r"(a[3]), "r"(b0), "r"(b1));
}

// ---------------- pre-kernel: W1 -> fp16, permuted k ----------------
__global__ void convert_w1_kernel(const float* __restrict__ W1) {
    int idx = blockIdx.x * blockDim.x + threadIdx.x;
    if (idx >= NTOT * KDIM) return;
    int k = idx & 127;
    int n = idx >> 7;
    int node = n >> 6, h = n & 63;
    int gnode = (1 << node) - 1;            // 0,1,3,7,15,31
    float v = W1[(size_t)gnode * (KDIM * 64) + (size_t)k * 64 + h];
    int blk = k >> 4, kk = k & 15, q = kk >> 1;
    int pos = (q & 3) * 2 + (q >> 2);
    g_Wh[n * KDIM + blk * 16 + pos * 2 + (kk & 1)] = __float2half_rn(v);
}

// ---------------- main kernel ----------------
__global__ __launch_bounds__(THREADS, 1)
void sdt_fp16_kernel(const float* __restrict__ x,
                     const float* __restrict__ b1,
                     const float* __restrict__ W2,
                     const float* __restrict__ b2,
                     const float* __restrict__ leaf,
                     float* __restrict__ out)
{
    extern __shared__ char smem[];
    const uint32_t sbase = smem_u32_of(smem);
    float* b1sh   = (float*)(smem + OFF_B1);
    float* W2s    = (float*)(smem + OFF_W2);
    float* b2s    = (float*)(smem + OFF_B2);
    float* leafs  = (float*)(smem + OFF_LEAF);
    float* rowsum = (float*)(smem + OFF_RS);

    const int tid  = threadIdx.x;
    const int lane = tid & 31;
    const int wid  = tid >> 5;
    const int wm   = wid & 1;               // M half (64 rows)
    const int wn   = wid >> 1;              // node (0..5)
    const int g    = lane >> 2;
    const int t4   = lane & 3;
    const int bx   = blockIdx.x;

    // ---- prologue: stage W (once) + raw X tile 0, linear addressing ----
    {
        uint32_t wdst = sbase + OFF_W + (uint32_t)((tid >> 4) * WPITCH + (tid & 15) * 16);
        const __half* wsrc = g_Wh + tid * 8;
        #pragma unroll
        for (int it = 0; it < 16; it++) {
            cp_async16(wdst, wsrc);
            wdst += 24 * WPITCH;            // 384 idx = 24 rows
            wsrc += 384 * 8;
        }
    }
    {
        const float* xsrc = x + (size_t)bx * TILES * M_CTA * KDIM + tid * 4;
        uint32_t xdst = sbase + OFF_XR + (uint32_t)tid * 16;
        #pragma unroll
        for (int it = 0; it < 11; it++) {
            if (it < 10 || tid < 256) cp_async16(xdst, xsrc);
            xsrc += 384 * 4;
            xdst += 6144;
        }
    }
    asm volatile("cp.async.commit_group;" ::: "memory");

    // small tensors for the 6 live nodes
    for (int i = tid; i < NTOT; i += THREADS) {
        int node = i >> 6, h = i & 63;
        int gl = ((1 << node) - 1) * 64 + h;
        b1sh[i] = b1[gl];
        W2s[i]  = W2[gl];
    }
    if (tid < 6)  b2s[tid]   = b2[(1 << tid) - 1];
    if (tid < 64) leafs[tid] = leaf[tid];

    asm volatile("cp.async.wait_group 0;" ::: "memory");
    __syncthreads();

    // hoisted convert addressing (it-invariant parts)
    const int c4i = tid & 31, mI = c4i & 3;
    const uint32_t cvt_src0 = sbase + OFF_XR + (uint32_t)tid * 16;
    const uint32_t cvt_dst0 = sbase + OFF_XC
        + (uint32_t)((tid >> 5) * XPITCH + (c4i >> 2) * 32
                     + ((mI & 1) * 4 + (mI >> 1)) * 4);

    const uint32_t xb = sbase + OFF_XC + (uint32_t)((wm * 64 + g) * XPITCH + t4 * 8);
    const uint32_t wb = sbase + OFF_W  + (uint32_t)((wn * 64 + g) * WPITCH + t4 * 8);

    for (int ti = 0; ti < TILES; ti++) {
        const int rowbase = (bx * TILES + ti) * M_CTA;

        // ---- convert raw X -> fp16 interleaved Xcvt (linear addrs) ----
        {
            uint32_t s = cvt_src0, d = cvt_dst0;
            #pragma unroll
            for (int it = 0; it < 11; it++) {
                if (it < 10 || tid < 256) {
                    float4 v;
                    lds128f(v, s);
                    __half2 h01 = __floats2half2_rn(v.x, v.y);
                    __half2 h23 = __floats2half2_rn(v.z, v.w);
                    sts32(d,     *(uint32_t*)&h01);
                    sts32(d + 8, *(uint32_t*)&h23);
                }
                s += 6144;
                d += 3456;                  // 12 rows * 288
            }
        }
        __syncthreads();

        // ---- prefetch raw X for next tile (overlaps MMA below) ----
        if (ti + 1 < TILES) {
            const float* xsrc = x + (size_t)(bx * TILES + ti + 1) * M_CTA * KDIM + tid * 4;
            uint32_t xdst = sbase + OFF_XR + (uint32_t)tid * 16;
            #pragma unroll
            for (int it = 0; it < 11; it++) {
                if (it < 10 || tid < 256) cp_async16(xdst, xsrc);
                xsrc += 384 * 4;
                xdst += 6144;
            }
            asm volatile("cp.async.commit_group;" ::: "memory");
        }

        // ---- MMA over N in two halves; acc regs reused; frag double-buffer ----
        float s0v[4] = {0.f, 0.f, 0.f, 0.f};
        float s1v[4] = {0.f, 0.f, 0.f, 0.f};

        #pragma unroll
        for (int h = 0; h < 2; h++) {
            const uint32_t wbh = wb + (uint32_t)(h * 32 * WPITCH);
            float acc[4][4][4];
            #pragma unroll
            for (int mt = 0; mt < 4; mt++)
                #pragma unroll
                for (int nt = 0; nt < 4; nt++)
                    #pragma unroll
                    for (int j = 0; j < 4; j++) acc[mt][nt][j] = 0.0f;

            uint32_t A[2][4][4], B[2][4][2];
            // preload k-step 0 into buffer 0
            #pragma unroll
            for (int mt = 0; mt < 4; mt++) {
                lds64(A[0][mt][0], A[0][mt][2], xb + (uint32_t)(mt * 16 * XPITCH));
                lds64(A[0][mt][1], A[0][mt][3], xb + (uint32_t)(mt * 16 * XPITCH) + 8 * XPITCH);
            }
            #pragma unroll
            for (int nt = 0; nt < 4; nt++)
                lds64(B[0][nt][0], B[0][nt][1], wbh + (uint32_t)(nt * 8 * WPITCH));

            #pragma unroll
            for (int ks = 0; ks < 8; ks++) {
                const int cur = ks & 1, nxt = cur ^ 1;
                if (ks < 7) {               // prefetch next k-step's fragments
                    const uint32_t ko = (uint32_t)((ks + 1) * 32);
                    #pragma unroll
                    for (int mt = 0; mt < 4; mt++) {
                        lds64(A[nxt][mt][0], A[nxt][mt][2],
                              xb + (uint32_t)(mt * 16 * XPITCH) + ko);
                        lds64(A[nxt][mt][1], A[nxt][mt][3],
                              xb + (uint32_t)(mt * 16 * XPITCH) + 8 * XPITCH + ko);
                    }
                    #pragma unroll
                    for (int nt = 0; nt < 4; nt++)
                        lds64(B[nxt][nt][0], B[nxt][nt][1],
                              wbh + (uint32_t)(nt * 8 * WPITCH) + ko);
                }
                #pragma unroll
                for (int nt = 0; nt < 4; nt++)
                    #pragma unroll
                    for (int mt = 0; mt < 4; mt++)
                        mma_fp16(acc[mt][nt], A[cur][mt], B[cur][nt][0], B[cur][nt][1]);
            }

            // epilogue partials for this half (accumulate across halves in regs)
            #pragma unroll
            for (int nt = 0; nt < 4; nt++) {
                int col = wn * 64 + h * 32 + nt * 8 + t4 * 2;
                float ba  = b1sh[col], bb = b1sh[col + 1];
                float wa  = W2s[col],  wbv = W2s[col + 1];
                #pragma unroll
                for (int mt = 0; mt < 4; mt++) {
                    s0v[mt] = fmaf(fmaxf(acc[mt][nt][0] + ba, 0.0f), wa,
                              fmaf(fmaxf(acc[mt][nt][1] + bb, 0.0f), wbv, s0v[mt]));
                    s1v[mt] = fmaf(fmaxf(acc[mt][nt][2] + ba, 0.0f), wa,
                              fmaf(fmaxf(acc[mt][nt][3] + bb, 0.0f), wbv, s1v[mt]));
                }
            }
        }

        // reduce across quad lanes, write rowsum (unique owner per slot)
        #pragma unroll
        for (int mt = 0; mt < 4; mt++) {
            float s0 = s0v[mt], s1 = s1v[mt];
            s0 += __shfl_xor_sync(0xffffffffu, s0, 1);
            s0 += __shfl_xor_sync(0xffffffffu, s0, 2);
            s1 += __shfl_xor_sync(0xffffffffu, s1, 1);
            s1 += __shfl_xor_sync(0xffffffffu, s1, 2);
            if (t4 == 0) {
                int r = wm * 64 + mt * 16 + g;
                rowsum[wn * 132 + r]     = s0;
                rowsum[wn * 132 + r + 8] = s1;
            }
        }
        __syncthreads();

        if (tid < M_CTA) {
            float p[6];
            #pragma unroll
            for (int k = 0; k < 6; k++) {
                float z = rowsum[k * 132 + tid] + b2s[k];
                p[k] = 1.0f / (1.0f + __expf(-z));
            }
            float v[32];
            #pragma unroll
            for (int m = 0; m < 32; m++)
                v[m] = fmaf(p[0], leafs[2 * m + 1], (1.0f - p[0]) * leafs[2 * m]);
            #pragma unroll
            for (int k = 1; k < 6; k++) {
                int len = 32 >> k;
                #pragma unroll
                for (int m = 0; m < 32; m++)
                    if (m < len)
                        v[m] = fmaf(p[k], v[2 * m + 1], (1.0f - p[k]) * v[2 * m]);
            }
            out[rowbase + tid] = v[0];
        }

        if (ti + 1 < TILES)
            asm volatile("cp.async.wait_group 0;" ::: "memory");
        __syncthreads();
    }
}

// ---------------- launch ----------------
extern "C" void kernel_launch(void* const* d_in, const int* in_sizes, int n_in,
                              void* d_out, int out_size)
{
    const float* x    = (const float*)d_in[0];
    const float* W1   = (const float*)d_in[1];
    const float* b1   = (const float*)d_in[2];
    const float* W2   = (const float*)d_in[3];
    const float* b2   = (const float*)d_in[4];
    const float* leaf = (const float*)d_in[5];
    float* out = (float*)d_out;

    cudaFuncSetAttribute(sdt_fp16_kernel, cudaFuncAttributeMaxDynamicSharedMemorySize, SMEM_BYTES);

    convert_w1_kernel<<<(NTOT * KDIM + 255) / 256, 256>>>(W1);
    sdt_fp16_kernel<<<NCTAS, THREADS, SMEM_BYTES>>>(x, b1, W2, b2, leaf, out);
}

// round 13
// speedup vs baseline: 1.8321x; 1.1180x over previous
#include <cuda_runtime.h>
#include <cuda_fp16.h>
#include <cstdint>

// Soft decision tree forward via mma.sync fp16 (family-common sm_103;
// tcgen05 unavailable in this toolchain path).
// Chain nodes (2^k)-1, k=0..5 -> N = 6*64 = 384.
// GEMM H = X[65536 x 128] @ W1cat[128 x 384], fp16 x fp16 -> **fp16 accumulate**
// (2x HMMA rate, half the acc registers; only 8 inter-MMA fp16 roundings per
// k=128 chain -> error ~ the existing fp16-input rounding). Epilogue in fp32:
// relu -> dot W2 -> sigmoid -> 6-level leaf fold.
// R13 = R9 persistent structure (128 CTAs x 4 M=128 tiles, W staged once,
// raw-X prefetch) + f16 accumulators + hoisted convert/table addressing.

#define THREADS 384      // 12 warps: wm = wid&1 (M half), wn = wid>>1 (node)
#define M_CTA   128
#define KDIM    128
#define NTOT    384
#define NCTAS   128
#define TILES   4
#define XPITCH  288      // bytes/row (72 words): conflict-free lds64
#define WPITCH  288

// W1 (live nodes) fp16, [n=384][k=128], k permuted within 16-blocks so that
// pairs (2t4,2t4+1) and (2t4+8,2t4+9) are adjacent -> frags = one LDS.64.
__device__ __align__(16) __half g_Wh[NTOT * KDIM];

// ---- smem layout (bytes) ----
#define OFF_B1    0
#define OFF_W2    1536
#define OFF_B2    3072
#define OFF_LEAF  3104
#define OFF_RS    3360                 // rowsum 6*132*4 = 3168 -> 6528
#define OFF_XC    6656                 // converted X: 128 * 288 = 36864
#define OFF_W     43520                // W: 384 * 288 = 110592
#define OFF_XR    154112               // raw X: 128 rows * 512B = 65536
#define SMEM_BYTES 219648              // ~214.5 KB, 1 CTA/SM

// ---------------- helpers ----------------
__device__ __forceinline__ uint32_t smem_u32_of(const void* p) {
    uint32_t a;
    asm("{ .reg .u64 t; cvta.to.shared.u64 t, %1; cvt.u32.u64 %0, t; }"
        : "=r"(a) : "l"(p));
    return a;
}
__device__ __forceinline__ void cp_async16(uint32_t dst, const void* src) {
    asm volatile("cp.async.cg.shared.global [%0], [%1], 16;" :: "r"(dst), "l"(src));
}
__device__ __forceinline__ void lds64(uint32_t& a, uint32_t& b, uint32_t addr) {
    asm volatile("ld.shared.v2.u32 {%0,%1}, [%2];" : "=r"(a), "=r"(b) : "r"(addr));
}
__device__ __forceinline__ void lds128f(float4& v, uint32_t addr) {
    asm volatile("ld.shared.v4.f32 {%0,%1,%2,%3}, [%4];"
                 : "=f"(v.x), "=f"(v.y), "=f"(v.z), "=f"(v.w) : "r"(addr));
}
__device__ __forceinline__ void sts32(uint32_t addr, uint32_t v) {
    asm volatile("st.shared.u32 [%0], %1;" :: "r"(addr), "r"(v));
}
// m16n8k16, all-fp16 (D/C fp16): 2-reg accumulator, 2x rate vs f32 acc
__device__ __forceinline__ void mma_f16acc(uint32_t* c, const uint32_t* a,
                                           uint32_t b0, uint32_t b1) {
    asm volatile(
        "mma.sync.aligned.m16n8k16.row.col.f16.f16.f16.f16 "
        "{%0,%1}, {%2,%3,%4,%5}, {%6,%7}, {%0,%1};"
        : "+r"(c[0]), "+r"(c[1])
        : "r"(a[0]), "r"(a[1]), "r"(a[2]), "r"(a[3]), "r"(b0), "r"(b1));
}

// ---------------- pre-kernel: W1 -> fp16, permuted k ----------------
__global__ void convert_w1_kernel(const float* __restrict__ W1) {
    int idx = blockIdx.x * blockDim.x + threadIdx.x;
    if (idx >= NTOT * KDIM) return;
    int k = idx & 127;
    int n = idx >> 7;
    int node = n >> 6, h = n & 63;
    int gnode = (1 << node) - 1;            // 0,1,3,7,15,31
    float v = W1[(size_t)gnode * (KDIM * 64) + (size_t)k * 64 + h];
    int blk = k >> 4, kk = k & 15, q = kk >> 1;
    int pos = (q & 3) * 2 + (q >> 2);
    g_Wh[n * KDIM + blk * 16 + pos * 2 + (kk & 1)] = __float2half_rn(v);
}

// ---------------- main kernel ----------------
__global__ __launch_bounds__(THREADS, 1)
void sdt_fp16_kernel(const float* __restrict__ x,
                     const float* __restrict__ b1,
                     const float* __restrict__ W2,
                     const float* __restrict__ b2,
                     const float* __restrict__ leaf,
                     float* __restrict__ out)
{
    extern __shared__ char smem[];
    const uint32_t sbase = smem_u32_of(smem);
    float* b1sh   = (float*)(smem + OFF_B1);
    float* W2s    = (float*)(smem + OFF_W2);
    float* b2s    = (float*)(smem + OFF_B2);
    float* leafs  = (float*)(smem + OFF_LEAF);
    float* rowsum = (float*)(smem + OFF_RS);

    const int tid  = threadIdx.x;
    const int lane = tid & 31;
    const int wid  = tid >> 5;
    const int wm   = wid & 1;               // M half (64 rows)
    const int wn   = wid >> 1;              // node (0..5)
    const int g    = lane >> 2;
    const int t4   = lane & 3;
    const int bx   = blockIdx.x;

    // ---- prologue: stage W (once) + raw X tile 0, linear addressing ----
    {
        uint32_t wdst = sbase + OFF_W + (uint32_t)((tid >> 4) * WPITCH + (tid & 15) * 16);
        const __half* wsrc = g_Wh + tid * 8;
        #pragma unroll
        for (int it = 0; it < 16; it++) {
            cp_async16(wdst, wsrc);
            wdst += 24 * WPITCH;            // 384 idx = 24 rows
            wsrc += 384 * 8;
        }
    }
    {
        const float* xsrc = x + (size_t)bx * TILES * M_CTA * KDIM + tid * 4;
        uint32_t xdst = sbase + OFF_XR + (uint32_t)tid * 16;
        #pragma unroll
        for (int it = 0; it < 11; it++) {
            if (it < 10 || tid < 256) cp_async16(xdst, xsrc);
            xsrc += 384 * 4;
            xdst += 6144;
        }
    }
    asm volatile("cp.async.commit_group;" ::: "memory");

    // small tensors for the 6 live nodes
    for (int i = tid; i < NTOT; i += THREADS) {
        int node = i >> 6, h = i & 63;
        int gl = ((1 << node) - 1) * 64 + h;
        b1sh[i] = b1[gl];
        W2s[i]  = W2[gl];
    }
    if (tid < 6)  b2s[tid]   = b2[(1 << tid) - 1];
    if (tid < 64) leafs[tid] = leaf[tid];

    asm volatile("cp.async.wait_group 0;" ::: "memory");
    __syncthreads();

    // hoisted convert addressing (iteration-invariant parts)
    const int c4i = tid & 31, mI = c4i & 3;
    const uint32_t cvt_src0 = sbase + OFF_XR + (uint32_t)tid * 16;
    const uint32_t cvt_dst0 = sbase + OFF_XC
        + (uint32_t)((tid >> 5) * XPITCH + (c4i >> 2) * 32
                     + ((mI & 1) * 4 + (mI >> 1)) * 4);

    const uint32_t xb = sbase + OFF_XC + (uint32_t)((wm * 64 + g) * XPITCH + t4 * 8);
    const uint32_t wb = sbase + OFF_W  + (uint32_t)((wn * 64 + g) * WPITCH + t4 * 8);

    // loop-invariant per-thread b1/W2 for this warp's 16 columns
    float b1v[16], W2v[16];
    #pragma unroll
    for (int nt = 0; nt < 8; nt++) {
        int col = wn * 64 + nt * 8 + t4 * 2;
        b1v[2 * nt]     = b1sh[col];
        b1v[2 * nt + 1] = b1sh[col + 1];
        W2v[2 * nt]     = W2s[col];
        W2v[2 * nt + 1] = W2s[col + 1];
    }

    for (int ti = 0; ti < TILES; ti++) {
        const int rowbase = (bx * TILES + ti) * M_CTA;

        // ---- convert raw X -> fp16 interleaved Xcvt (linear addrs) ----
        {
            uint32_t s = cvt_src0, d = cvt_dst0;
            #pragma unroll
            for (int it = 0; it < 11; it++) {
                if (it < 10 || tid < 256) {
                    float4 v;
                    lds128f(v, s);
                    __half2 h01 = __floats2half2_rn(v.x, v.y);
                    __half2 h23 = __floats2half2_rn(v.z, v.w);
                    sts32(d,     *(uint32_t*)&h01);
                    sts32(d + 8, *(uint32_t*)&h23);
                }
                s += 6144;
                d += 3456;                  // 12 rows * 288
            }
        }
        __syncthreads();

        // ---- prefetch raw X for next tile (overlaps MMA below) ----
        if (ti + 1 < TILES) {
            const float* xsrc = x + (size_t)(bx * TILES + ti + 1) * M_CTA * KDIM + tid * 4;
            uint32_t xdst = sbase + OFF_XR + (uint32_t)tid * 16;
            #pragma unroll
            for (int it = 0; it < 11; it++) {
                if (it < 10 || tid < 256) cp_async16(xdst, xsrc);
                xsrc += 384 * 4;
                xdst += 6144;
            }
            asm volatile("cp.async.commit_group;" ::: "memory");
        }

        // ---- MMA: 8 k-steps over full k=128, fp16 accumulators ----
        uint32_t acc[4][8][2];
        #pragma unroll
        for (int mt = 0; mt < 4; mt++)
            #pragma unroll
            for (int nt = 0; nt < 8; nt++) {
                acc[mt][nt][0] = 0u;
                acc[mt][nt][1] = 0u;
            }

        #pragma unroll
        for (int ks = 0; ks < 8; ks++) {
            const uint32_t ko = (uint32_t)(ks * 32);
            uint32_t A[4][4];
            #pragma unroll
            for (int mt = 0; mt < 4; mt++) {
                lds64(A[mt][0], A[mt][2], xb + (uint32_t)(mt * 16 * XPITCH) + ko);
                lds64(A[mt][1], A[mt][3], xb + (uint32_t)(mt * 16 * XPITCH) + 8 * XPITCH + ko);
            }
            #pragma unroll
            for (int nt = 0; nt < 8; nt++) {
                uint32_t b0, b1f;
                lds64(b0, b1f, wb + (uint32_t)(nt * 8 * WPITCH) + ko);
                #pragma unroll
                for (int mt = 0; mt < 4; mt++)
                    mma_f16acc(acc[mt][nt], A[mt], b0, b1f);
            }
        }

        // ---- fused epilogue (fp32): relu -> dot W2 ----
        #pragma unroll
        for (int mt = 0; mt < 4; mt++) {
            float s0 = 0.0f, s1 = 0.0f;
            #pragma unroll
            for (int nt = 0; nt < 8; nt++) {
                float2 f0 = __half22float2(*reinterpret_cast<__half2*>(&acc[mt][nt][0]));
                float2 f1 = __half22float2(*reinterpret_cast<__half2*>(&acc[mt][nt][1]));
                s0 = fmaf(fmaxf(f0.x + b1v[2 * nt], 0.0f),     W2v[2 * nt], s0);
                s0 = fmaf(fmaxf(f0.y + b1v[2 * nt + 1], 0.0f), W2v[2 * nt + 1], s0);
                s1 = fmaf(fmaxf(f1.x + b1v[2 * nt], 0.0f),     W2v[2 * nt], s1);
                s1 = fmaf(fmaxf(f1.y + b1v[2 * nt + 1], 0.0f), W2v[2 * nt + 1], s1);
            }
            s0 += __shfl_xor_sync(0xffffffffu, s0, 1);
            s0 += __shfl_xor_sync(0xffffffffu, s0, 2);
            s1 += __shfl_xor_sync(0xffffffffu, s1, 1);
            s1 += __shfl_xor_sync(0xffffffffu, s1, 2);
            if (t4 == 0) {
                int r = wm * 64 + mt * 16 + g;
                rowsum[wn * 132 + r]     = s0;
                rowsum[wn * 132 + r + 8] = s1;
            }
        }
        __syncthreads();

        if (tid < M_CTA) {
            float p[6];
            #pragma unroll
            for (int k = 0; k < 6; k++) {
                float z = rowsum[k * 132 + tid] + b2s[k];
                p[k] = 1.0f / (1.0f + __expf(-z));
            }
            float v[32];
            #pragma unroll
            for (int m = 0; m < 32; m++)
                v[m] = fmaf(p[0], leafs[2 * m + 1], (1.0f - p[0]) * leafs[2 * m]);
            #pragma unroll
            for (int k = 1; k < 6; k++) {
                int len = 32 >> k;
                #pragma unroll
                for (int m = 0; m < 32; m++)
                    if (m < len)
                        v[m] = fmaf(p[k], v[2 * m + 1], (1.0f - p[k]) * v[2 * m]);
            }
            out[rowbase + tid] = v[0];
        }

        if (ti + 1 < TILES)
            asm volatile("cp.async.wait_group 0;" ::: "memory");
        __syncthreads();
    }
}

// ---------------- launch ----------------
extern "C" void kernel_launch(void* const* d_in, const int* in_sizes, int n_in,
                              void* d_out, int out_size)
{
    const float* x    = (const float*)d_in[0];
    const float* W1   = (const float*)d_in[1];
    const float* b1   = (const float*)d_in[2];
    const float* W2   = (const float*)d_in[3];
    const float* b2   = (const float*)d_in[4];
    const float* leaf = (const float*)d_in[5];
    float* out = (float*)d_out;

    cudaFuncSetAttribute(sdt_fp16_kernel, cudaFuncAttributeMaxDynamicSharedMemorySize, SMEM_BYTES);

    convert_w1_kernel<<<(NTOT * KDIM + 255) / 256, 256>>>(W1);
    sdt_fp16_kernel<<<NCTAS, THREADS, SMEM_BYTES>>>(x, b1, W2, b2, leaf, out);
}